// round 14
// baseline (speedup 1.0000x reference)
#include <cuda_runtime.h>
#include <cuda_fp16.h>
#include <cstdint>

// ===========================================================================
// Submanifold 3x3x3 sparse conv, N~1e5, Cin=Cout=64, fp32 in/out.
// R14: R12 dense fp16 mma.sync skeleton, re-tiled for latency hiding:
//   64-row tiles, 128 threads, ~39KB smem -> occupancy 5-6 blocks/SM,
//   single __syncthreads per tap (bottom barrier proven redundant).
// Baseline-PTX only (sm_100 target safe).
// ===========================================================================

#define HASH_BITS 18
#define HASH_SIZE (1u << HASH_BITS)
#define HASH_MASK (HASH_SIZE - 1u)
#define MAX_PROBE 4096
#define MAXN      131072

__device__ unsigned long long g_hkeys[HASH_SIZE];
__device__ int                g_hvals[HASH_SIZE];

// fp16 features [MAXN][64]; fp16 transposed weights pre-swizzled (SW128)
__device__ uint4 g_Af4[MAXN * 64 * 2 / 16];
__device__ uint4 g_Wf4[27 * 8192 / 16];

__device__ __forceinline__ unsigned hash_mix(unsigned long long z) {
    z ^= z >> 30; z *= 0xbf58476d1ce4e5b9ULL;
    z ^= z >> 27; z *= 0x94d049bb133111ebULL;
    z ^= z >> 31;
    return (unsigned)z & HASH_MASK;
}

#define SW128(off) ((off) ^ (((off) >> 3) & 0x70))

// ---- fused prep: hash init + feat->fp16 + weight transpose/swizzle ----
__global__ void fused_prep_kernel(const float4* __restrict__ feat4, int total4,
                                  const float* __restrict__ weight, int welems) {
    int i = blockIdx.x * blockDim.x + threadIdx.x;
    if (i < (int)HASH_SIZE) { g_hkeys[i] = ~0ULL; g_hvals[i] = 0x7fffffff; }
    if (i < total4) {
        float4 x = feat4[i];
        __half2 lo = __floats2half2_rn(x.x, x.y);
        __half2 hi = __floats2half2_rn(x.z, x.w);
        ((uint2*)g_Af4)[i] = make_uint2(*(unsigned*)&lo, *(unsigned*)&hi);
    }
    if (i < 27 * 4096) {
        int k    = i >> 12;
        int cin  = (i >> 6) & 63;
        int cout = i & 63;
        float x = (i < welems) ? weight[i] : 0.0f;
        unsigned off = SW128((unsigned)(cout * 128 + cin * 2));
        ((__half*)g_Wf4)[((unsigned)k * 8192 + off) >> 1] = __float2half_rn(x);
    }
}

__global__ void hash_insert_kernel(const int* __restrict__ coords,
                                   const int* __restrict__ batch_idx,
                                   int n, int coords_elems, int batch_elems) {
    int i = blockIdx.x * blockDim.x + threadIdx.x;
    if (i >= n) return;
    int c0 = (3 * i + 0 < coords_elems) ? coords[3 * i + 0] : 0;
    int c1 = (3 * i + 1 < coords_elems) ? coords[3 * i + 1] : 0;
    int c2 = (3 * i + 2 < coords_elems) ? coords[3 * i + 2] : 0;
    int b  = (i < batch_elems) ? batch_idx[i] : 0;
    long long x = (long long)c0 + (long long)b * 100000LL;
    unsigned long long key = ((unsigned long long)x << 40) |
                             ((unsigned long long)(long long)c1 << 20) |
                             ((unsigned long long)(long long)c2);
    unsigned s = hash_mix(key);
    for (int p = 0; p < MAX_PROBE; p++) {
        unsigned long long prev = atomicCAS(&g_hkeys[s & HASH_MASK], ~0ULL, key);
        if (prev == ~0ULL || prev == key) {
            atomicMin(&g_hvals[s & HASH_MASK], i);   // min-index tie-break
            return;
        }
        s = (s + 1) & HASH_MASK;
    }
}

__device__ __forceinline__ int hash_lookup(unsigned long long key, int n) {
    unsigned s = hash_mix(key);
    for (int p = 0; p < MAX_PROBE; p++) {
        unsigned long long k = g_hkeys[s & HASH_MASK];
        if (k == key) {
            int v = g_hvals[s & HASH_MASK];
            return (v >= 0 && v < n) ? v : -1;
        }
        if (k == ~0ULL) return -1;
        s = (s + 1) & HASH_MASK;
    }
    return -1;
}

__global__ void zero_out_kernel(float* out, int nelem) {
    int i = blockIdx.x * blockDim.x + threadIdx.x;
    if (i < nelem) out[i] = 0.0f;
}

// ===========================================================================
// Conv kernel. One block = 64-row tile, 128 threads (4 warps).
// Warp grid 2(m) x 2(n): warp w -> rows [(w>>1)*32,+32), cols [(w&1)*32,+32).
// smem (dynamic):
//   A[2 bufs] 8KB each -> 0 .. 16K    (64 rows x 128B, SW128)
//   B[2 bufs] 8KB each -> 16K .. 32K  (64 rows x 128B, SW128)
//   nbr 27*64 ints     -> 32K (6912B)   total 39680B -> occupancy 5
// Pipeline: iter k: wait_group 0 -> sync -> stage(k+1, other buf) -> mma(k).
// Single barrier per tap (top sync covers buffer-reuse hazard).
// ===========================================================================

#define SM_A(buf)  ((unsigned)((buf) * 8192))
#define SM_B(buf)  ((unsigned)(16384 + (buf) * 8192))
#define SM_NBR     (32768u)
#define SMEM_TOTAL (32768 + 6912)

__device__ __forceinline__ unsigned smem_u32(const void* p) {
    unsigned a;
    asm("{ .reg .u64 t; cvta.to.shared.u64 t, %1; cvt.u32.u64 %0, t; }"
        : "=r"(a) : "l"(p));
    return a;
}

__device__ __forceinline__ void ldsm_x4(unsigned addr, unsigned r[4]) {
    asm volatile("ldmatrix.sync.aligned.m8n8.x4.shared.b16 {%0,%1,%2,%3}, [%4];"
                 : "=r"(r[0]), "=r"(r[1]), "=r"(r[2]), "=r"(r[3]) : "r"(addr));
}

__global__ __launch_bounds__(128, 5)
void subm_conv_mma_kernel(const int*   __restrict__ coords,
                          const int*   __restrict__ batch_idx,
                          float*       __restrict__ out,
                          int n, int coords_elems, int batch_elems) {
    extern __shared__ char smem[];
    const unsigned sbase = smem_u32(smem);
    const int tid  = threadIdx.x;
    const int wid  = tid >> 5;
    const int lane = tid & 31;
    const int row0 = blockIdx.x * 64;

    int* nbrS = (int*)(smem + SM_NBR);

    // ---- neighbor table: 27 taps x 64 rows (clamped reads) ----
    for (int e = tid; e < 27 * 64; e += 128) {
        int k = e >> 6;
        int r = e & 63;
        int row = row0 + r;
        int nb = -1;
        if (row < n) {
            int dx = (k / 9) - 1, dy = ((k / 3) % 3) - 1, dz = (k % 3) - 1;
            int c0 = (3 * row + 0 < coords_elems) ? coords[3 * row + 0] : 0;
            int c1 = (3 * row + 1 < coords_elems) ? coords[3 * row + 1] : 0;
            int c2 = (3 * row + 2 < coords_elems) ? coords[3 * row + 2] : 0;
            int b  = (row < batch_elems) ? batch_idx[row] : 0;
            long long x = (long long)c0 + (long long)b * 100000LL + dx;
            long long y = (long long)c1 + dy;
            long long z = (long long)c2 + dz;
            unsigned long long key = ((unsigned long long)x << 40) |
                                     ((unsigned long long)y << 20) |
                                     ((unsigned long long)z);
            nb = hash_lookup(key, n);
        }
        nbrS[e] = nb;
    }
    __syncthreads();

    const __half* Af = (const __half*)g_Af4;

    // Async staging: A = gather (zero-fill masked rows), B = linear copy.
    // A: 512 16B-chunks -> 4/thread. B: 512 -> 4/thread. One commit group.
#define STAGE_TAP_ASYNC(kk, buf)                                              \
    {                                                                         \
        const int* nb_k = &nbrS[(kk) * 64];                                   \
        _Pragma("unroll")                                                     \
        for (int q = 0; q < 4; q++) {                                         \
            int e = tid + q * 128;                                            \
            int r = e >> 3, ch = e & 7;                                       \
            int nb = nb_k[r];                                                 \
            const void* gsrc = Af + (size_t)(nb < 0 ? 0 : nb) * 64 + ch * 8;  \
            unsigned ssize = (nb >= 0) ? 16u : 0u;                            \
            unsigned boff  = (unsigned)(r * 128 + ch * 16);                   \
            unsigned daddr = sbase + SM_A(buf) + SW128(boff);                 \
            asm volatile("cp.async.ca.shared.global [%0], [%1], 16, %2;"      \
                         :: "r"(daddr), "l"(gsrc), "r"(ssize) : "memory");    \
        }                                                                     \
        _Pragma("unroll")                                                     \
        for (int q = 0; q < 4; q++) {                                         \
            int e = tid + q * 128;                                            \
            const uint4* src = g_Wf4 + (kk) * 512 + e;                        \
            unsigned daddr = sbase + SM_B(buf) + e * 16;                      \
            asm volatile("cp.async.ca.shared.global [%0], [%1], 16;"          \
                         :: "r"(daddr), "l"(src) : "memory");                 \
        }                                                                     \
        asm volatile("cp.async.commit_group;" ::: "memory");                  \
    }

    STAGE_TAP_ASYNC(0, 0)

    float acc[4][4];   // warp covers m32 (2 m16 tiles) x n32 (4 n8 tiles)
    float acc2[4][4];
#pragma unroll
    for (int j = 0; j < 4; j++)
#pragma unroll
        for (int c = 0; c < 4; c++) { acc[j][c] = 0.0f; acc2[j][c] = 0.0f; }

    const int mrow0 = (wid >> 1) * 32;   // warp m-strip (0/32)
    const int nb0   = (wid & 1) * 32;    // warp n-half (0/32)

    const int a_row = lane & 15;
    const int a_kc  = lane >> 4;
    const int b_row = ((lane >> 4) << 3) + (lane & 7);
    const int b_kc  = (lane >> 3) & 1;

    for (int k = 0; k < 27; k++) {
        const int buf = k & 1;
        asm volatile("cp.async.wait_group 0;" ::: "memory");
        __syncthreads();   // tap k staged + everyone past compute(k-1)

        if (k + 1 < 27) STAGE_TAP_ASYNC(k + 1, (k + 1) & 1)

        const unsigned abase = sbase + SM_A(buf);
        const unsigned bbase = sbase + SM_B(buf);

#pragma unroll
        for (int kk = 0; kk < 4; kk++) {
            unsigned af0[4], af1[4];
            {
                unsigned boff = (unsigned)((mrow0 + a_row) * 128 +
                                           (kk * 2 + a_kc) * 16);
                ldsm_x4(abase + SW128(boff), af0);
                unsigned boff1 = (unsigned)((mrow0 + 16 + a_row) * 128 +
                                            (kk * 2 + a_kc) * 16);
                ldsm_x4(abase + SW128(boff1), af1);
            }
            unsigned bf[2][4];
#pragma unroll
            for (int nt = 0; nt < 2; nt++) {
                unsigned boff = (unsigned)((nb0 + nt * 16 + b_row) * 128 +
                                           (kk * 2 + b_kc) * 16);
                ldsm_x4(bbase + SW128(boff), bf[nt]);
            }
#pragma unroll
            for (int j = 0; j < 4; j++) {
                asm volatile(
                    "mma.sync.aligned.m16n8k16.row.col.f32.f16.f16.f32 "
                    "{%0,%1,%2,%3}, {%4,%5,%6,%7}, {%8,%9}, {%0,%1,%2,%3};"
                    : "+f"(acc[j][0]), "+f"(acc[j][1]),
                      "+f"(acc[j][2]), "+f"(acc[j][3])
                    : "r"(af0[0]), "r"(af0[1]), "r"(af0[2]), "r"(af0[3]),
                      "r"(bf[j >> 1][(j & 1) * 2]),
                      "r"(bf[j >> 1][(j & 1) * 2 + 1]));
                asm volatile(
                    "mma.sync.aligned.m16n8k16.row.col.f32.f16.f16.f32 "
                    "{%0,%1,%2,%3}, {%4,%5,%6,%7}, {%8,%9}, {%0,%1,%2,%3};"
                    : "+f"(acc2[j][0]), "+f"(acc2[j][1]),
                      "+f"(acc2[j][2]), "+f"(acc2[j][3])
                    : "r"(af1[0]), "r"(af1[1]), "r"(af1[2]), "r"(af1[3]),
                      "r"(bf[j >> 1][(j & 1) * 2]),
                      "r"(bf[j >> 1][(j & 1) * 2 + 1]));
            }
        }
        // no bottom barrier: next iteration's wait_group+sync covers reuse
    }

    // ---- store: D frag rows = lane>>2 (+8), cols = (lane&3)*2 ----
    const int r_lo  = lane >> 2;
    const int c_off = (lane & 3) * 2;
#pragma unroll
    for (int j = 0; j < 4; j++) {
        int col = nb0 + j * 8 + c_off;
        int rowA = row0 + mrow0 + r_lo;
        if (rowA < n)
            *(float2*)(out + (size_t)rowA * 64 + col) =
                make_float2(acc[j][0], acc[j][1]);
        if (rowA + 8 < n)
            *(float2*)(out + (size_t)(rowA + 8) * 64 + col) =
                make_float2(acc[j][2], acc[j][3]);
        int rowB = rowA + 16;
        if (rowB < n)
            *(float2*)(out + (size_t)rowB * 64 + col) =
                make_float2(acc2[j][0], acc2[j][1]);
        if (rowB + 8 < n)
            *(float2*)(out + (size_t)(rowB + 8) * 64 + col) =
                make_float2(acc2[j][2], acc2[j][3]);
    }
}

// ---------------------------------------------------------------------------
// Launch. Binding inferred from in_sizes ratios (unit-agnostic), as in R6.
// ---------------------------------------------------------------------------
extern "C" void kernel_launch(void* const* d_in, const int* in_sizes, int n_in,
                              void* d_out, int out_size) {
    float* out = (float*)d_out;

    int wi = -1;
    bool bytes_mode = false;
    for (int i = 0; i < n_in; i++) {
        if (in_sizes[i] == 27 * 64 * 64)          { wi = i; bytes_mode = false; }
        else if (in_sizes[i] == 27 * 64 * 64 * 4) { wi = i; bytes_mode = true;  }
    }
    int bi = -1, ci = -1, fi = -1;
    for (int b = 0; b < n_in && bi < 0; b++) {
        if (b == wi) continue;
        long long s = in_sizes[b];
        if (s <= 0) continue;
        int c = -1, f = -1;
        for (int j = 0; j < n_in; j++) {
            if (j == b || j == wi) continue;
            if ((long long)in_sizes[j] == s * 3)  c = j;
            if ((long long)in_sizes[j] == s * 64) f = j;
        }
        if (c >= 0 && f >= 0) { bi = b; ci = c; fi = f; }
    }

    if (wi < 0 || bi < 0) {
        int nelem = out_size > 0 ? out_size : 1;
        zero_out_kernel<<<(nelem + 255) / 256, 256>>>(out, nelem);
        return;
    }

    const int div          = bytes_mode ? 4 : 1;
    const int n            = in_sizes[bi] / div;
    const int batch_elems  = in_sizes[bi] / div;
    const int coords_elems = in_sizes[ci] / div;
    const int feat_elems   = in_sizes[fi] / div;
    const int weight_elems = in_sizes[wi] / div;

    if (n <= 0 || n > MAXN) {
        int nelem = out_size > 0 ? out_size : 1;
        zero_out_kernel<<<(nelem + 255) / 256, 256>>>(out, nelem);
        return;
    }

    const float* feat   = (const float*)d_in[fi];
    const int*   coords = (const int*)d_in[ci];
    const int*   batch  = (const int*)d_in[bi];
    const float* weight = (const float*)d_in[wi];

    // Idempotent, no static guards; non-stream API is capture-safe.
    cudaFuncSetAttribute(subm_conv_mma_kernel,
                         cudaFuncAttributeMaxDynamicSharedMemorySize,
                         SMEM_TOTAL);

    const int feat4 = feat_elems / 4;
    int prep_threads = feat4;
    if ((int)HASH_SIZE > prep_threads) prep_threads = HASH_SIZE;
    if (27 * 4096 > prep_threads)      prep_threads = 27 * 4096;

    fused_prep_kernel<<<(prep_threads + 255) / 256, 256>>>(
        (const float4*)feat, feat4, weight, weight_elems);
    hash_insert_kernel<<<(n + 255) / 256, 256>>>(coords, batch, n,
                                                 coords_elems, batch_elems);
    subm_conv_mma_kernel<<<(n + 63) / 64, 128, SMEM_TOTAL>>>(
        coords, batch, out, n, coords_elems, batch_elems);
}

// round 15
// speedup vs baseline: 1.1294x; 1.1294x over previous
#include <cuda_runtime.h>
#include <cuda_fp16.h>
#include <cstdint>

// ===========================================================================
// Submanifold 3x3x3 sparse conv, N~1e5, Cin=Cout=64, fp32 in/out.
// R15: R12 dense fp16 mma.sync skeleton (proven best) with B moved out of
// the smem pipeline: weights pre-laid-out in mma-fragment-linear order in
// global memory, loaded per tap as 8 coalesced LDG.128 into registers
// (issued before the barrier so the barrier wait hides L2 latency).
// Removes all B cp.async + B smem traffic + 1/3 of ldsm.
// Baseline-PTX only (sm_100 target safe).
// ===========================================================================

#define HASH_BITS 18
#define HASH_SIZE (1u << HASH_BITS)
#define HASH_MASK (HASH_SIZE - 1u)
#define MAX_PROBE 4096
#define MAXN      131072

__device__ unsigned long long g_hkeys[HASH_SIZE];
__device__ int                g_hvals[HASH_SIZE];

// fp16 features [MAXN][64]
__device__ uint4 g_Af4[MAXN * 64 * 2 / 16];
// fragment-linear fp16 weights: [tap][nh][kk][jj][lane] uint4
//   27 * 2 * 4 * 2 * 32 = 13824 uint4 (216 KB)
__device__ uint4 g_Bf4[27 * 2 * 4 * 2 * 32];

__device__ __forceinline__ unsigned hash_mix(unsigned long long z) {
    z ^= z >> 30; z *= 0xbf58476d1ce4e5b9ULL;
    z ^= z >> 27; z *= 0x94d049bb133111ebULL;
    z ^= z >> 31;
    return (unsigned)z & HASH_MASK;
}

#define SW128(off) ((off) ^ (((off) >> 3) & 0x70))

// ---- fused prep: hash init + feat->fp16 + weight -> fragment-linear ----
__global__ void fused_prep_kernel(const float4* __restrict__ feat4, int total4,
                                  const float* __restrict__ weight, int welems) {
    int i = blockIdx.x * blockDim.x + threadIdx.x;
    if (i < (int)HASH_SIZE) { g_hkeys[i] = ~0ULL; g_hvals[i] = 0x7fffffff; }
    if (i < total4) {
        float4 x = feat4[i];
        __half2 lo = __floats2half2_rn(x.x, x.y);
        __half2 hi = __floats2half2_rn(x.z, x.w);
        ((uint2*)g_Af4)[i] = make_uint2(*(unsigned*)&lo, *(unsigned*)&hi);
    }
    // B fragment-linear: i over 27*2048 b32 regs
    if (i < 27 * 2048) {
        int r    = i & 3;          // reg within lane's uint4
        int lane = (i >> 2) & 31;
        int jj   = (i >> 7) & 1;
        int kk   = (i >> 8) & 3;
        int nh   = (i >> 10) & 1;
        int tap  = i >> 11;
        int j      = jj * 2 + (r >> 1);     // n8 tile within warp n32
        int regsel = r & 1;                 // K 0-7 vs 8-15
        int cin0   = kk * 16 + regsel * 8 + (lane & 3) * 2;
        int cout   = nh * 32 + j * 8 + (lane >> 2);
        int w0 = (tap * 64 + cin0) * 64 + cout;
        int w1 = (tap * 64 + cin0 + 1) * 64 + cout;
        float x0 = (w0 < welems) ? weight[w0] : 0.0f;
        float x1 = (w1 < welems) ? weight[w1] : 0.0f;
        __half2 h = __floats2half2_rn(x0, x1);   // low = cin0 (K first)
        ((unsigned*)g_Bf4)[i] = *(unsigned*)&h;
    }
}

__global__ void hash_insert_kernel(const int* __restrict__ coords,
                                   const int* __restrict__ batch_idx,
                                   int n, int coords_elems, int batch_elems) {
    int i = blockIdx.x * blockDim.x + threadIdx.x;
    if (i >= n) return;
    int c0 = (3 * i + 0 < coords_elems) ? coords[3 * i + 0] : 0;
    int c1 = (3 * i + 1 < coords_elems) ? coords[3 * i + 1] : 0;
    int c2 = (3 * i + 2 < coords_elems) ? coords[3 * i + 2] : 0;
    int b  = (i < batch_elems) ? batch_idx[i] : 0;
    long long x = (long long)c0 + (long long)b * 100000LL;
    unsigned long long key = ((unsigned long long)x << 40) |
                             ((unsigned long long)(long long)c1 << 20) |
                             ((unsigned long long)(long long)c2);
    unsigned s = hash_mix(key);
    for (int p = 0; p < MAX_PROBE; p++) {
        unsigned long long prev = atomicCAS(&g_hkeys[s & HASH_MASK], ~0ULL, key);
        if (prev == ~0ULL || prev == key) {
            atomicMin(&g_hvals[s & HASH_MASK], i);   // min-index tie-break
            return;
        }
        s = (s + 1) & HASH_MASK;
    }
}

__device__ __forceinline__ int hash_lookup(unsigned long long key, int n) {
    unsigned s = hash_mix(key);
    for (int p = 0; p < MAX_PROBE; p++) {
        unsigned long long k = g_hkeys[s & HASH_MASK];
        if (k == key) {
            int v = g_hvals[s & HASH_MASK];
            return (v >= 0 && v < n) ? v : -1;
        }
        if (k == ~0ULL) return -1;
        s = (s + 1) & HASH_MASK;
    }
    return -1;
}

__global__ void zero_out_kernel(float* out, int nelem) {
    int i = blockIdx.x * blockDim.x + threadIdx.x;
    if (i < nelem) out[i] = 0.0f;
}

// ===========================================================================
// Conv kernel. One block = 128-row tile, 256 threads (8 warps), grid 4m x 2n.
// smem (dynamic):
//   A[2 bufs] 16KB each -> 0 .. 32K   (128 rows x 128B, SW128)
//   nbr 27*128 ints     -> 32K (13824B)   total 46592B
// Pipeline per tap k: [B LDGs for k into regs] -> wait_group 0 -> sync ->
//   stage A(k+1) -> ldsm A + mma (B from regs). Single barrier per tap.
// ===========================================================================

#define SM_A(buf)  ((unsigned)((buf) * 16384))
#define SM_NBR     (32768u)
#define SMEM_TOTAL (32768 + 13824)

__device__ __forceinline__ unsigned smem_u32(const void* p) {
    unsigned a;
    asm("{ .reg .u64 t; cvta.to.shared.u64 t, %1; cvt.u32.u64 %0, t; }"
        : "=r"(a) : "l"(p));
    return a;
}

__device__ __forceinline__ void ldsm_x4(unsigned addr, unsigned r[4]) {
    asm volatile("ldmatrix.sync.aligned.m8n8.x4.shared.b16 {%0,%1,%2,%3}, [%4];"
                 : "=r"(r[0]), "=r"(r[1]), "=r"(r[2]), "=r"(r[3]) : "r"(addr));
}

__global__ __launch_bounds__(256, 3)
void subm_conv_mma_kernel(const int*   __restrict__ coords,
                          const int*   __restrict__ batch_idx,
                          float*       __restrict__ out,
                          int n, int coords_elems, int batch_elems) {
    extern __shared__ char smem[];
    const unsigned sbase = smem_u32(smem);
    const int tid  = threadIdx.x;
    const int wid  = tid >> 5;
    const int lane = tid & 31;
    const int row0 = blockIdx.x * 128;

    int* nbrS = (int*)(smem + SM_NBR);

    // ---- neighbor table: 27 taps x 128 rows (clamped reads) ----
    for (int e = tid; e < 27 * 128; e += 256) {
        int k = e >> 7;
        int r = e & 127;
        int row = row0 + r;
        int nb = -1;
        if (row < n) {
            int dx = (k / 9) - 1, dy = ((k / 3) % 3) - 1, dz = (k % 3) - 1;
            int c0 = (3 * row + 0 < coords_elems) ? coords[3 * row + 0] : 0;
            int c1 = (3 * row + 1 < coords_elems) ? coords[3 * row + 1] : 0;
            int c2 = (3 * row + 2 < coords_elems) ? coords[3 * row + 2] : 0;
            int b  = (row < batch_elems) ? batch_idx[row] : 0;
            long long x = (long long)c0 + (long long)b * 100000LL + dx;
            long long y = (long long)c1 + dy;
            long long z = (long long)c2 + dz;
            unsigned long long key = ((unsigned long long)x << 40) |
                                     ((unsigned long long)y << 20) |
                                     ((unsigned long long)z);
            nb = hash_lookup(key, n);
        }
        nbrS[e] = nb;
    }
    __syncthreads();

    const __half* Af = (const __half*)g_Af4;

    // A staging: gather (zero-fill masked rows). 1024 16B-chunks -> 4/thread.
#define STAGE_A_ASYNC(kk, buf)                                                \
    {                                                                         \
        const int* nb_k = &nbrS[(kk) * 128];                                  \
        _Pragma("unroll")                                                     \
        for (int q = 0; q < 4; q++) {                                         \
            int e = tid + q * 256;                                            \
            int r = e >> 3, ch = e & 7;                                       \
            int nb = nb_k[r];                                                 \
            const void* gsrc = Af + (size_t)(nb < 0 ? 0 : nb) * 64 + ch * 8;  \
            unsigned ssize = (nb >= 0) ? 16u : 0u;                            \
            unsigned boff  = (unsigned)(r * 128 + ch * 16);                   \
            unsigned daddr = sbase + SM_A(buf) + SW128(boff);                 \
            asm volatile("cp.async.ca.shared.global [%0], [%1], 16, %2;"      \
                         :: "r"(daddr), "l"(gsrc), "r"(ssize) : "memory");    \
        }                                                                     \
        asm volatile("cp.async.commit_group;" ::: "memory");                  \
    }

    STAGE_A_ASYNC(0, 0)

    float acc[2][4][4];
#pragma unroll
    for (int t = 0; t < 2; t++)
#pragma unroll
        for (int j = 0; j < 4; j++)
#pragma unroll
            for (int c = 0; c < 4; c++) acc[t][j][c] = 0.0f;

    const int mrow0 = (wid >> 1) * 32;   // warp m-strip (0/32/64/96)
    const int nh    = (wid & 1);         // warp n-half (0/1)
    const int nb0   = nh * 32;

    const int a_row = lane & 15;
    const int a_kc  = lane >> 4;

    // per-warp fragment-linear B base (uint4 units): [tap][nh][kk][jj][lane]
    const uint4* Bwarp = g_Bf4 + (size_t)lane;

    for (int k = 0; k < 27; k++) {
        const int buf = k & 1;

        // ---- B for tap k: 8 coalesced LDG.128 into regs (pre-barrier,
        //      their L2 latency overlaps the barrier wait) ----
        uint4 bq[8];
        {
            const uint4* bp = Bwarp + (size_t)((k * 2 + nh) * 8) * 32;
#pragma unroll
            for (int f = 0; f < 8; f++) bq[f] = bp[(size_t)f * 32];
        }

        asm volatile("cp.async.wait_group 0;" ::: "memory");
        __syncthreads();   // A(k) staged + all warps past compute(k-1)

        if (k + 1 < 27) STAGE_A_ASYNC(k + 1, (k + 1) & 1)

        const unsigned abase = sbase + SM_A(buf);

#pragma unroll
        for (int kk = 0; kk < 4; kk++) {
            unsigned af0[4], af1[4];
            {
                unsigned boff = (unsigned)((mrow0 + a_row) * 128 +
                                           (kk * 2 + a_kc) * 16);
                ldsm_x4(abase + SW128(boff), af0);
                unsigned boff1 = (unsigned)((mrow0 + 16 + a_row) * 128 +
                                            (kk * 2 + a_kc) * 16);
                ldsm_x4(abase + SW128(boff1), af1);
            }
#pragma unroll
            for (int j = 0; j < 4; j++) {
                const uint4 bv = bq[kk * 2 + (j >> 1)];
                unsigned b0 = (j & 1) ? bv.z : bv.x;
                unsigned b1 = (j & 1) ? bv.w : bv.y;
                asm volatile(
                    "mma.sync.aligned.m16n8k16.row.col.f32.f16.f16.f32 "
                    "{%0,%1,%2,%3}, {%4,%5,%6,%7}, {%8,%9}, {%0,%1,%2,%3};"
                    : "+f"(acc[0][j][0]), "+f"(acc[0][j][1]),
                      "+f"(acc[0][j][2]), "+f"(acc[0][j][3])
                    : "r"(af0[0]), "r"(af0[1]), "r"(af0[2]), "r"(af0[3]),
                      "r"(b0), "r"(b1));
                asm volatile(
                    "mma.sync.aligned.m16n8k16.row.col.f32.f16.f16.f32 "
                    "{%0,%1,%2,%3}, {%4,%5,%6,%7}, {%8,%9}, {%0,%1,%2,%3};"
                    : "+f"(acc[1][j][0]), "+f"(acc[1][j][1]),
                      "+f"(acc[1][j][2]), "+f"(acc[1][j][3])
                    : "r"(af1[0]), "r"(af1[1]), "r"(af1[2]), "r"(af1[3]),
                      "r"(b0), "r"(b1));
            }
        }
        // single barrier per tap: next iteration's wait+sync covers reuse
    }

    // ---- store: D frag rows = lane>>2 (+8), cols = (lane&3)*2 ----
    const int r_lo  = lane >> 2;
    const int c_off = (lane & 3) * 2;
#pragma unroll
    for (int t = 0; t < 2; t++)
#pragma unroll
        for (int j = 0; j < 4; j++) {
            int row = row0 + mrow0 + t * 16 + r_lo;
            int col = nb0 + j * 8 + c_off;
            if (row < n)
                *(float2*)(out + (size_t)row * 64 + col) =
                    make_float2(acc[t][j][0], acc[t][j][1]);
            if (row + 8 < n)
                *(float2*)(out + (size_t)(row + 8) * 64 + col) =
                    make_float2(acc[t][j][2], acc[t][j][3]);
        }
}

// ---------------------------------------------------------------------------
// Launch. Binding inferred from in_sizes ratios (unit-agnostic), as in R6.
// ---------------------------------------------------------------------------
extern "C" void kernel_launch(void* const* d_in, const int* in_sizes, int n_in,
                              void* d_out, int out_size) {
    float* out = (float*)d_out;

    int wi = -1;
    bool bytes_mode = false;
    for (int i = 0; i < n_in; i++) {
        if (in_sizes[i] == 27 * 64 * 64)          { wi = i; bytes_mode = false; }
        else if (in_sizes[i] == 27 * 64 * 64 * 4) { wi = i; bytes_mode = true;  }
    }
    int bi = -1, ci = -1, fi = -1;
    for (int b = 0; b < n_in && bi < 0; b++) {
        if (b == wi) continue;
        long long s = in_sizes[b];
        if (s <= 0) continue;
        int c = -1, f = -1;
        for (int j = 0; j < n_in; j++) {
            if (j == b || j == wi) continue;
            if ((long long)in_sizes[j] == s * 3)  c = j;
            if ((long long)in_sizes[j] == s * 64) f = j;
        }
        if (c >= 0 && f >= 0) { bi = b; ci = c; fi = f; }
    }

    if (wi < 0 || bi < 0) {
        int nelem = out_size > 0 ? out_size : 1;
        zero_out_kernel<<<(nelem + 255) / 256, 256>>>(out, nelem);
        return;
    }

    const int div          = bytes_mode ? 4 : 1;
    const int n            = in_sizes[bi] / div;
    const int batch_elems  = in_sizes[bi] / div;
    const int coords_elems = in_sizes[ci] / div;
    const int feat_elems   = in_sizes[fi] / div;
    const int weight_elems = in_sizes[wi] / div;

    if (n <= 0 || n > MAXN) {
        int nelem = out_size > 0 ? out_size : 1;
        zero_out_kernel<<<(nelem + 255) / 256, 256>>>(out, nelem);
        return;
    }

    const float* feat   = (const float*)d_in[fi];
    const int*   coords = (const int*)d_in[ci];
    const int*   batch  = (const int*)d_in[bi];
    const float* weight = (const float*)d_in[wi];

    // Idempotent, no static guards; non-stream API is capture-safe.
    cudaFuncSetAttribute(subm_conv_mma_kernel,
                         cudaFuncAttributeMaxDynamicSharedMemorySize,
                         SMEM_TOTAL);

    const int feat4 = feat_elems / 4;
    int prep_threads = feat4;
    if ((int)HASH_SIZE > prep_threads) prep_threads = HASH_SIZE;
    if (27 * 2048 > prep_threads)      prep_threads = 27 * 2048;

    fused_prep_kernel<<<(prep_threads + 255) / 256, 256>>>(
        (const float4*)feat, feat4, weight, weight_elems);
    hash_insert_kernel<<<(n + 255) / 256, 256>>>(coords, batch, n,
                                                 coords_elems, batch_elems);
    subm_conv_mma_kernel<<<(n + 127) / 128, 256, SMEM_TOTAL>>>(
        coords, batch, out, n, coords_elems, batch_elems);
}

// round 16
// speedup vs baseline: 1.1342x; 1.0042x over previous
#include <cuda_runtime.h>
#include <cuda_fp16.h>
#include <cstdint>

// ===========================================================================
// Submanifold 3x3x3 sparse conv, N~1e5, Cin=Cout=64, fp32 in/out.
// R16: R15 (B fragment-linear in registers) + 3-stage depth-2 A prefetch.
//   A-only smem: 3 x 16KB stages + nbr = 62KB -> occupancy 3 retained.
//   Iter k: load B(k) regs -> wait_group 1 (tap k landed; k+1 in flight)
//   -> sync -> stage A(k+2) -> mma(k).  Depth-2 hides full gather latency.
// Baseline-PTX only (sm_100 target safe).
// ===========================================================================

#define HASH_BITS 18
#define HASH_SIZE (1u << HASH_BITS)
#define HASH_MASK (HASH_SIZE - 1u)
#define MAX_PROBE 4096
#define MAXN      131072

__device__ unsigned long long g_hkeys[HASH_SIZE];
__device__ int                g_hvals[HASH_SIZE];

// fp16 features [MAXN][64]
__device__ uint4 g_Af4[MAXN * 64 * 2 / 16];
// fragment-linear fp16 weights: [tap][nh][kk][jj][lane] uint4 (216 KB)
__device__ uint4 g_Bf4[27 * 2 * 4 * 2 * 32];

__device__ __forceinline__ unsigned hash_mix(unsigned long long z) {
    z ^= z >> 30; z *= 0xbf58476d1ce4e5b9ULL;
    z ^= z >> 27; z *= 0x94d049bb133111ebULL;
    z ^= z >> 31;
    return (unsigned)z & HASH_MASK;
}

#define SW128(off) ((off) ^ (((off) >> 3) & 0x70))

// ---- fused prep: hash init + feat->fp16 + weight -> fragment-linear ----
__global__ void fused_prep_kernel(const float4* __restrict__ feat4, int total4,
                                  const float* __restrict__ weight, int welems) {
    int i = blockIdx.x * blockDim.x + threadIdx.x;
    if (i < (int)HASH_SIZE) { g_hkeys[i] = ~0ULL; g_hvals[i] = 0x7fffffff; }
    if (i < total4) {
        float4 x = feat4[i];
        __half2 lo = __floats2half2_rn(x.x, x.y);
        __half2 hi = __floats2half2_rn(x.z, x.w);
        ((uint2*)g_Af4)[i] = make_uint2(*(unsigned*)&lo, *(unsigned*)&hi);
    }
    // B fragment-linear: i over 27*2048 b32 regs
    if (i < 27 * 2048) {
        int r    = i & 3;          // reg within lane's uint4
        int lane = (i >> 2) & 31;
        int jj   = (i >> 7) & 1;
        int kk   = (i >> 8) & 3;
        int nh   = (i >> 10) & 1;
        int tap  = i >> 11;
        int j      = jj * 2 + (r >> 1);     // n8 tile within warp n32
        int regsel = r & 1;                 // K 0-7 vs 8-15
        int cin0   = kk * 16 + regsel * 8 + (lane & 3) * 2;
        int cout   = nh * 32 + j * 8 + (lane >> 2);
        int w0 = (tap * 64 + cin0) * 64 + cout;
        int w1 = (tap * 64 + cin0 + 1) * 64 + cout;
        float x0 = (w0 < welems) ? weight[w0] : 0.0f;
        float x1 = (w1 < welems) ? weight[w1] : 0.0f;
        __half2 h = __floats2half2_rn(x0, x1);   // low = cin0 (K first)
        ((unsigned*)g_Bf4)[i] = *(unsigned*)&h;
    }
}

__global__ void hash_insert_kernel(const int* __restrict__ coords,
                                   const int* __restrict__ batch_idx,
                                   int n, int coords_elems, int batch_elems) {
    int i = blockIdx.x * blockDim.x + threadIdx.x;
    if (i >= n) return;
    int c0 = (3 * i + 0 < coords_elems) ? coords[3 * i + 0] : 0;
    int c1 = (3 * i + 1 < coords_elems) ? coords[3 * i + 1] : 0;
    int c2 = (3 * i + 2 < coords_elems) ? coords[3 * i + 2] : 0;
    int b  = (i < batch_elems) ? batch_idx[i] : 0;
    long long x = (long long)c0 + (long long)b * 100000LL;
    unsigned long long key = ((unsigned long long)x << 40) |
                             ((unsigned long long)(long long)c1 << 20) |
                             ((unsigned long long)(long long)c2);
    unsigned s = hash_mix(key);
    for (int p = 0; p < MAX_PROBE; p++) {
        unsigned long long prev = atomicCAS(&g_hkeys[s & HASH_MASK], ~0ULL, key);
        if (prev == ~0ULL || prev == key) {
            atomicMin(&g_hvals[s & HASH_MASK], i);   // min-index tie-break
            return;
        }
        s = (s + 1) & HASH_MASK;
    }
}

__device__ __forceinline__ int hash_lookup(unsigned long long key, int n) {
    unsigned s = hash_mix(key);
    for (int p = 0; p < MAX_PROBE; p++) {
        unsigned long long k = g_hkeys[s & HASH_MASK];
        if (k == key) {
            int v = g_hvals[s & HASH_MASK];
            return (v >= 0 && v < n) ? v : -1;
        }
        if (k == ~0ULL) return -1;
        s = (s + 1) & HASH_MASK;
    }
    return -1;
}

__global__ void zero_out_kernel(float* out, int nelem) {
    int i = blockIdx.x * blockDim.x + threadIdx.x;
    if (i < nelem) out[i] = 0.0f;
}

// ===========================================================================
// Conv kernel. One block = 128-row tile, 256 threads (8 warps), grid 4m x 2n.
// smem (dynamic): A[3 stages] 16KB each -> 0..48K ; nbr 13824B -> 48K..62.2K
// ===========================================================================

#define SM_A(buf)  ((unsigned)((buf) * 16384))
#define SM_NBR     (49152u)
#define SMEM_TOTAL (49152 + 13824)

__device__ __forceinline__ unsigned smem_u32(const void* p) {
    unsigned a;
    asm("{ .reg .u64 t; cvta.to.shared.u64 t, %1; cvt.u32.u64 %0, t; }"
        : "=r"(a) : "l"(p));
    return a;
}

__device__ __forceinline__ void ldsm_x4(unsigned addr, unsigned r[4]) {
    asm volatile("ldmatrix.sync.aligned.m8n8.x4.shared.b16 {%0,%1,%2,%3}, [%4];"
                 : "=r"(r[0]), "=r"(r[1]), "=r"(r[2]), "=r"(r[3]) : "r"(addr));
}

__global__ __launch_bounds__(256, 3)
void subm_conv_mma_kernel(const int*   __restrict__ coords,
                          const int*   __restrict__ batch_idx,
                          float*       __restrict__ out,
                          int n, int coords_elems, int batch_elems) {
    extern __shared__ char smem[];
    const unsigned sbase = smem_u32(smem);
    const int tid  = threadIdx.x;
    const int wid  = tid >> 5;
    const int lane = tid & 31;
    const int row0 = blockIdx.x * 128;

    int* nbrS = (int*)(smem + SM_NBR);

    // ---- neighbor table: 27 taps x 128 rows (clamped reads) ----
    for (int e = tid; e < 27 * 128; e += 256) {
        int k = e >> 7;
        int r = e & 127;
        int row = row0 + r;
        int nb = -1;
        if (row < n) {
            int dx = (k / 9) - 1, dy = ((k / 3) % 3) - 1, dz = (k % 3) - 1;
            int c0 = (3 * row + 0 < coords_elems) ? coords[3 * row + 0] : 0;
            int c1 = (3 * row + 1 < coords_elems) ? coords[3 * row + 1] : 0;
            int c2 = (3 * row + 2 < coords_elems) ? coords[3 * row + 2] : 0;
            int b  = (row < batch_elems) ? batch_idx[row] : 0;
            long long x = (long long)c0 + (long long)b * 100000LL + dx;
            long long y = (long long)c1 + dy;
            long long z = (long long)c2 + dz;
            unsigned long long key = ((unsigned long long)x << 40) |
                                     ((unsigned long long)y << 20) |
                                     ((unsigned long long)z);
            nb = hash_lookup(key, n);
        }
        nbrS[e] = nb;
    }
    __syncthreads();

    const __half* Af = (const __half*)g_Af4;

    // A staging: gather (zero-fill masked rows). 1024 16B-chunks -> 4/thread.
#define STAGE_A_ASYNC(kk, buf)                                                \
    {                                                                         \
        const int* nb_k = &nbrS[(kk) * 128];                                  \
        _Pragma("unroll")                                                     \
        for (int q = 0; q < 4; q++) {                                         \
            int e = tid + q * 256;                                            \
            int r = e >> 3, ch = e & 7;                                       \
            int nb = nb_k[r];                                                 \
            const void* gsrc = Af + (size_t)(nb < 0 ? 0 : nb) * 64 + ch * 8;  \
            unsigned ssize = (nb >= 0) ? 16u : 0u;                            \
            unsigned boff  = (unsigned)(r * 128 + ch * 16);                   \
            unsigned daddr = sbase + SM_A(buf) + SW128(boff);                 \
            asm volatile("cp.async.ca.shared.global [%0], [%1], 16, %2;"      \
                         :: "r"(daddr), "l"(gsrc), "r"(ssize) : "memory");    \
        }                                                                     \
        asm volatile("cp.async.commit_group;" ::: "memory");                  \
    }

    // prologue: depth-2 prefetch (taps 0 and 1)
    STAGE_A_ASYNC(0, 0)
    STAGE_A_ASYNC(1, 1)

    float acc[2][4][4];
#pragma unroll
    for (int t = 0; t < 2; t++)
#pragma unroll
        for (int j = 0; j < 4; j++)
#pragma unroll
            for (int c = 0; c < 4; c++) acc[t][j][c] = 0.0f;

    const int mrow0 = (wid >> 1) * 32;   // warp m-strip (0/32/64/96)
    const int nh    = (wid & 1);         // warp n-half (0/1)
    const int nb0   = nh * 32;

    const int a_row = lane & 15;
    const int a_kc  = lane >> 4;

    // per-warp fragment-linear B base (uint4 units): [tap][nh][kk][jj][lane]
    const uint4* Bwarp = g_Bf4 + (size_t)lane;

    int buf = 0;   // k % 3 tracked incrementally
    for (int k = 0; k < 27; k++) {
        // ---- B for tap k: 8 coalesced LDG.128 into regs (pre-barrier;
        //      their L2 latency overlaps the wait below) ----
        uint4 bq[8];
        {
            const uint4* bp = Bwarp + (size_t)((k * 2 + nh) * 8) * 32;
#pragma unroll
            for (int f = 0; f < 8; f++) bq[f] = bp[(size_t)f * 32];
        }

        // wait until tap k's A gather has landed:
        //   while 2 groups may be outstanding -> wait_group 1
        //   tail (k >= 25): <=1 outstanding -> wait_group 0
        if (k < 25) {
            asm volatile("cp.async.wait_group 1;" ::: "memory");
        } else {
            asm volatile("cp.async.wait_group 0;" ::: "memory");
        }
        __syncthreads();   // A(k) visible to all warps; all past compute(k-1)

        // stage tap k+2 into buf (k+2)%3 (last read by compute(k-1), fenced)
        int buf2 = buf + 2; if (buf2 >= 3) buf2 -= 3;
        if (k + 2 < 27) STAGE_A_ASYNC(k + 2, buf2)

        const unsigned abase = sbase + SM_A(buf);

#pragma unroll
        for (int kk = 0; kk < 4; kk++) {
            unsigned af0[4], af1[4];
            {
                unsigned boff = (unsigned)((mrow0 + a_row) * 128 +
                                           (kk * 2 + a_kc) * 16);
                ldsm_x4(abase + SW128(boff), af0);
                unsigned boff1 = (unsigned)((mrow0 + 16 + a_row) * 128 +
                                            (kk * 2 + a_kc) * 16);
                ldsm_x4(abase + SW128(boff1), af1);
            }
#pragma unroll
            for (int j = 0; j < 4; j++) {
                const uint4 bv = bq[kk * 2 + (j >> 1)];
                unsigned b0 = (j & 1) ? bv.z : bv.x;
                unsigned b1 = (j & 1) ? bv.w : bv.y;
                asm volatile(
                    "mma.sync.aligned.m16n8k16.row.col.f32.f16.f16.f32 "
                    "{%0,%1,%2,%3}, {%4,%5,%6,%7}, {%8,%9}, {%0,%1,%2,%3};"
                    : "+f"(acc[0][j][0]), "+f"(acc[0][j][1]),
                      "+f"(acc[0][j][2]), "+f"(acc[0][j][3])
                    : "r"(af0[0]), "r"(af0[1]), "r"(af0[2]), "r"(af0[3]),
                      "r"(b0), "r"(b1));
                asm volatile(
                    "mma.sync.aligned.m16n8k16.row.col.f32.f16.f16.f32 "
                    "{%0,%1,%2,%3}, {%4,%5,%6,%7}, {%8,%9}, {%0,%1,%2,%3};"
                    : "+f"(acc[1][j][0]), "+f"(acc[1][j][1]),
                      "+f"(acc[1][j][2]), "+f"(acc[1][j][3])
                    : "r"(af1[0]), "r"(af1[1]), "r"(af1[2]), "r"(af1[3]),
                      "r"(b0), "r"(b1));
            }
        }
        buf = buf + 1; if (buf >= 3) buf -= 3;
        // single barrier per tap: next iteration's wait+sync covers reuse
    }

    // ---- store: D frag rows = lane>>2 (+8), cols = (lane&3)*2 ----
    const int r_lo  = lane >> 2;
    const int c_off = (lane & 3) * 2;
#pragma unroll
    for (int t = 0; t < 2; t++)
#pragma unroll
        for (int j = 0; j < 4; j++) {
            int row = row0 + mrow0 + t * 16 + r_lo;
            int col = nb0 + j * 8 + c_off;
            if (row < n)
                *(float2*)(out + (size_t)row * 64 + col) =
                    make_float2(acc[t][j][0], acc[t][j][1]);
            if (row + 8 < n)
                *(float2*)(out + (size_t)(row + 8) * 64 + col) =
                    make_float2(acc[t][j][2], acc[t][j][3]);
        }
}

// ---------------------------------------------------------------------------
// Launch. Binding inferred from in_sizes ratios (unit-agnostic), as in R6.
// ---------------------------------------------------------------------------
extern "C" void kernel_launch(void* const* d_in, const int* in_sizes, int n_in,
                              void* d_out, int out_size) {
    float* out = (float*)d_out;

    int wi = -1;
    bool bytes_mode = false;
    for (int i = 0; i < n_in; i++) {
        if (in_sizes[i] == 27 * 64 * 64)          { wi = i; bytes_mode = false; }
        else if (in_sizes[i] == 27 * 64 * 64 * 4) { wi = i; bytes_mode = true;  }
    }
    int bi = -1, ci = -1, fi = -1;
    for (int b = 0; b < n_in && bi < 0; b++) {
        if (b == wi) continue;
        long long s = in_sizes[b];
        if (s <= 0) continue;
        int c = -1, f = -1;
        for (int j = 0; j < n_in; j++) {
            if (j == b || j == wi) continue;
            if ((long long)in_sizes[j] == s * 3)  c = j;
            if ((long long)in_sizes[j] == s * 64) f = j;
        }
        if (c >= 0 && f >= 0) { bi = b; ci = c; fi = f; }
    }

    if (wi < 0 || bi < 0) {
        int nelem = out_size > 0 ? out_size : 1;
        zero_out_kernel<<<(nelem + 255) / 256, 256>>>(out, nelem);
        return;
    }

    const int div          = bytes_mode ? 4 : 1;
    const int n            = in_sizes[bi] / div;
    const int batch_elems  = in_sizes[bi] / div;
    const int coords_elems = in_sizes[ci] / div;
    const int feat_elems   = in_sizes[fi] / div;
    const int weight_elems = in_sizes[wi] / div;

    if (n <= 0 || n > MAXN) {
        int nelem = out_size > 0 ? out_size : 1;
        zero_out_kernel<<<(nelem + 255) / 256, 256>>>(out, nelem);
        return;
    }

    const float* feat   = (const float*)d_in[fi];
    const int*   coords = (const int*)d_in[ci];
    const int*   batch  = (const int*)d_in[bi];
    const float* weight = (const float*)d_in[wi];

    // Idempotent, no static guards; non-stream API is capture-safe.
    cudaFuncSetAttribute(subm_conv_mma_kernel,
                         cudaFuncAttributeMaxDynamicSharedMemorySize,
                         SMEM_TOTAL);

    const int feat4 = feat_elems / 4;
    int prep_threads = feat4;
    if ((int)HASH_SIZE > prep_threads) prep_threads = HASH_SIZE;
    if (27 * 2048 > prep_threads)      prep_threads = 27 * 2048;

    fused_prep_kernel<<<(prep_threads + 255) / 256, 256>>>(
        (const float4*)feat, feat4, weight, weight_elems);
    hash_insert_kernel<<<(n + 255) / 256, 256>>>(coords, batch, n,
                                                 coords_elems, batch_elems);
    subm_conv_mma_kernel<<<(n + 127) / 128, 256, SMEM_TOTAL>>>(
        coords, batch, out, n, coords_elems, batch_elems);
}